// round 4
// baseline (speedup 1.0000x reference)
#include <cuda_runtime.h>
#include <cuda_bf16.h>
#include <cstdint>

#define UNITS 512
#define VOCAB 32000
#define BATCH 128
#define SEQ   64
#define ROWS  (BATCH * SEQ)   // 8192

// ---------------- scratch (no allocations allowed) ----------------
__device__ float g_score[ROWS];
__device__ float g_xc[BATCH * 2 * UNITS];
__device__ float g_y[BATCH * UNITS];

__device__ __forceinline__ float sigmoidf_(float x) { return 1.0f / (1.0f + expf(-x)); }

__device__ __forceinline__ uint32_t f2tf32(float x) {
    uint32_t u;
    asm("cvt.rna.tf32.f32 %0, %1;" : "=r"(u) : "f"(x));
    return u;
}

__device__ __forceinline__ uint32_t smem_u32(const void* p) {
    return (uint32_t)__cvta_generic_to_shared(p);
}

#define CP16(dst, src) asm volatile("cp.async.cg.shared.global [%0], [%1], 16;" :: "r"(dst), "l"(src))
#define CP_COMMIT()    asm volatile("cp.async.commit_group;")
#define CP_WAIT2()     asm volatile("cp.async.wait_group 2;")

__device__ __forceinline__ void mma_tf32(float c[4], uint32_t a0, uint32_t a1,
                                         uint32_t a2, uint32_t a3,
                                         uint32_t b0, uint32_t b1) {
    asm volatile(
        "mma.sync.aligned.m16n8k8.row.col.f32.tf32.tf32.f32 "
        "{%0,%1,%2,%3}, {%4,%5,%6,%7}, {%8,%9}, {%0,%1,%2,%3};"
        : "+f"(c[0]), "+f"(c[1]), "+f"(c[2]), "+f"(c[3])
        : "r"(a0), "r"(a1), "r"(a2), "r"(a3), "r"(b0), "r"(b1));
}

// =================================================================
// TF32 tensor-core GEMM, 128x128x16 tile, 4-stage cp.async pipeline,
// 256 threads (8 warps 2x4, 64x32 warp tile).
// EPI=0: C = A@B + bias (ACT=1 -> relu)
// EPI=1: attention epilogue: tanh(acc + b0 + b1).vW -> atomic g_score
// dynamic smem layout: As[4][128][20] | Bs[4][16][136] | rowsum[128]
// =================================================================
#define AS_STRIDE 20
#define BS_STRIDE 136
#define AS_FLOATS (4 * 128 * AS_STRIDE)
#define BS_FLOATS (4 * 16 * BS_STRIDE)
#define GEMM_SMEM_BYTES ((AS_FLOATS + BS_FLOATS + 128) * sizeof(float))

template<int EPI, int ACT>
__global__ __launch_bounds__(256) void tf32_gemm(
    const float* __restrict__ A, const float* __restrict__ B,
    const float* __restrict__ bias, float* __restrict__ C,
    int M, int N, int K,
    const float* __restrict__ b1v, const float* __restrict__ vW)
{
    extern __shared__ float smem[];
    float (*As)[128][AS_STRIDE] = (float(*)[128][AS_STRIDE])smem;
    float (*Bs)[16][BS_STRIDE]  = (float(*)[16][BS_STRIDE])(smem + AS_FLOATS);
    float* rowsum = smem + AS_FLOATS + BS_FLOATS;

    const int tid  = threadIdx.x;
    const int lane = tid & 31;
    const int warp = tid >> 5;
    const int wm = warp >> 2;          // 0..1
    const int wn = warp & 3;           // 0..3
    const int q = lane & 3, r = lane >> 2;

    const int row0 = blockIdx.y * 128;
    const int col0 = blockIdx.x * 128;

    // async-copy mapping: A tile 128x16 f32 (512x16B), B tile 16x128 (512x16B); 2+2 per thread
    const int a_row = tid >> 2;        // 0..63
    const int a_c4  = tid & 3;
    const int b_k   = tid >> 5;        // 0..7
    const int b_c4  = tid & 31;

    const float* Ag0 = A + (size_t)(row0 + a_row) * K + a_c4 * 4;
    const float* Ag1 = Ag0 + (size_t)64 * K;
    const float* Bg0 = B + (size_t)b_k * N + col0 + b_c4 * 4;
    const float* Bg1 = Bg0 + (size_t)8 * N;

    const uint32_t sa0 = smem_u32(&As[0][a_row][a_c4 * 4]);
    const uint32_t sa1 = smem_u32(&As[0][a_row + 64][a_c4 * 4]);
    const uint32_t sb0 = smem_u32(&Bs[0][b_k][b_c4 * 4]);
    const uint32_t sb1 = smem_u32(&Bs[0][b_k + 8][b_c4 * 4]);
    const uint32_t a_stage = 128 * AS_STRIDE * 4;  // bytes per A stage
    const uint32_t b_stage = 16 * BS_STRIDE * 4;   // bytes per B stage

    const int nkt = K / 16;

    auto issue = [&](int kt) {
        const int s = kt & 3;
        const size_t ko = (size_t)kt * 16;
        CP16(sa0 + s * a_stage, Ag0 + ko);
        CP16(sa1 + s * a_stage, Ag1 + ko);
        CP16(sb0 + s * b_stage, Bg0 + ko * N);
        CP16(sb1 + s * b_stage, Bg1 + ko * N);
        CP_COMMIT();
    };

    issue(0); issue(1); issue(2);

    float c[4][4][4];
    #pragma unroll
    for (int i = 0; i < 4; i++)
        #pragma unroll
        for (int j = 0; j < 4; j++)
            #pragma unroll
            for (int k = 0; k < 4; k++) c[i][j][k] = 0.0f;

    for (int kt = 0; kt < nkt; kt++) {
        CP_WAIT2();
        __syncthreads();
        if (kt + 3 < nkt) issue(kt + 3);
        const int buf = kt & 3;

        #pragma unroll
        for (int kk = 0; kk < 2; kk++) {
            const int kb = kk * 8;
            uint32_t af[4][4], bf[4][2];
            #pragma unroll
            for (int i = 0; i < 4; i++) {
                int row = wm * 64 + i * 16 + r;
                af[i][0] = f2tf32(As[buf][row][kb + q]);
                af[i][1] = f2tf32(As[buf][row + 8][kb + q]);
                af[i][2] = f2tf32(As[buf][row][kb + q + 4]);
                af[i][3] = f2tf32(As[buf][row + 8][kb + q + 4]);
            }
            #pragma unroll
            for (int j = 0; j < 4; j++) {
                int col = wn * 32 + j * 8 + r;
                bf[j][0] = f2tf32(Bs[buf][kb + q][col]);
                bf[j][1] = f2tf32(Bs[buf][kb + q + 4][col]);
            }
            #pragma unroll
            for (int i = 0; i < 4; i++)
                #pragma unroll
                for (int j = 0; j < 4; j++)
                    mma_tf32(c[i][j], af[i][0], af[i][1], af[i][2], af[i][3],
                             bf[j][0], bf[j][1]);
        }
    }

    if (EPI == 0) {
        #pragma unroll
        for (int i = 0; i < 4; i++) {
            int rr = row0 + wm * 64 + i * 16 + r;
            #pragma unroll
            for (int j = 0; j < 4; j++) {
                int cc = col0 + wn * 32 + j * 8 + 2 * q;
                float bia0 = bias[cc], bia1 = bias[cc + 1];
                float v00 = c[i][j][0] + bia0, v01 = c[i][j][1] + bia1;
                float v10 = c[i][j][2] + bia0, v11 = c[i][j][3] + bia1;
                if (ACT) {
                    v00 = fmaxf(v00, 0.f); v01 = fmaxf(v01, 0.f);
                    v10 = fmaxf(v10, 0.f); v11 = fmaxf(v11, 0.f);
                }
                *(float2*)&C[(size_t)rr * N + cc]       = make_float2(v00, v01);
                *(float2*)&C[(size_t)(rr + 8) * N + cc] = make_float2(v10, v11);
            }
        }
    } else {
        __syncthreads();
        if (tid < 128) rowsum[tid] = 0.0f;
        __syncthreads();
        #pragma unroll
        for (int i = 0; i < 4; i++) {
            float s_lo = 0.0f, s_hi = 0.0f;
            #pragma unroll
            for (int j = 0; j < 4; j++) {
                int cc = col0 + wn * 32 + j * 8 + 2 * q;
                float w0 = vW[cc], w1 = vW[cc + 1];
                float bb0 = bias[cc] + b1v[cc];
                float bb1 = bias[cc + 1] + b1v[cc + 1];
                s_lo += tanhf(c[i][j][0] + bb0) * w0 + tanhf(c[i][j][1] + bb1) * w1;
                s_hi += tanhf(c[i][j][2] + bb0) * w0 + tanhf(c[i][j][3] + bb1) * w1;
            }
            s_lo += __shfl_xor_sync(0xffffffffu, s_lo, 1);
            s_lo += __shfl_xor_sync(0xffffffffu, s_lo, 2);
            s_hi += __shfl_xor_sync(0xffffffffu, s_hi, 1);
            s_hi += __shfl_xor_sync(0xffffffffu, s_hi, 2);
            if (q == 0) {
                atomicAdd(&rowsum[wm * 64 + i * 16 + r], s_lo);
                atomicAdd(&rowsum[wm * 64 + i * 16 + r + 8], s_hi);
            }
        }
        __syncthreads();
        if (tid < 128) atomicAdd(&g_score[row0 + tid], rowsum[tid]);
    }
}

// ---------------- fused softmax + context + emb gather -> g_xc, out_alpha ----
__global__ __launch_bounds__(256) void attn_reduce_kernel(
    const float* __restrict__ attn, const int* __restrict__ inp,
    const float* __restrict__ emb, float* __restrict__ out_alpha)
{
    __shared__ float sa[SEQ];
    __shared__ float4 part[128];
    const int b = blockIdx.x, t = threadIdx.x;

    if (t < 32) {
        float v0 = g_score[b * SEQ + t];
        float v1 = g_score[b * SEQ + 32 + t];
        float m = fmaxf(v0, v1);
        #pragma unroll
        for (int off = 16; off > 0; off >>= 1)
            m = fmaxf(m, __shfl_xor_sync(0xffffffffu, m, off));
        float e0 = expf(v0 - m), e1 = expf(v1 - m);
        float s = e0 + e1;
        #pragma unroll
        for (int off = 16; off > 0; off >>= 1)
            s += __shfl_xor_sync(0xffffffffu, s, off);
        float a0 = e0 / s, a1 = e1 / s;
        sa[t] = a0; sa[32 + t] = a1;
        out_alpha[b * SEQ + t] = a0;
        out_alpha[b * SEQ + 32 + t] = a1;
    }
    __syncthreads();

    const int col4 = t & 127;
    const int half = t >> 7;
    const float4* base = (const float4*)(attn + (size_t)b * SEQ * UNITS) + col4;
    float4 acc = make_float4(0.f, 0.f, 0.f, 0.f);
    const int s0 = half * 32;
    #pragma unroll 8
    for (int s = s0; s < s0 + 32; s++) {
        float4 v = base[(size_t)s * (UNITS / 4)];
        float a = sa[s];
        acc.x += v.x * a; acc.y += v.y * a; acc.z += v.z * a; acc.w += v.w * a;
    }
    if (half) part[col4] = acc;
    __syncthreads();
    if (!half) {
        float4 p = part[col4];
        acc.x += p.x; acc.y += p.y; acc.z += p.z; acc.w += p.w;
        ((float4*)(g_xc + (size_t)b * 2 * UNITS + UNITS))[col4] = acc;
    } else {
        float4 e = ((const float4*)(emb + (size_t)inp[b] * UNITS))[col4];
        ((float4*)(g_xc + (size_t)b * 2 * UNITS))[col4] = e;
    }
}

// ---------------- fused gates GEMM + GRU nonlinearity (h = 0) -------------
// xc[128,1024] @ gru_k[1024,1536] -> z|r|h gates -> state[128,512]
__global__ __launch_bounds__(256) void gru_fused_kernel(
    const float* __restrict__ gru_k, const float* __restrict__ gru_b,
    float* __restrict__ out_state)
{
    __shared__ float As[32][33];
    __shared__ float Bs[3][32][33];
    const int tid = threadIdx.x;
    const int tr = tid >> 4;   // 0..15
    const int tc = tid & 15;   // 0..15
    const int row0 = blockIdx.y * 32;
    const int col0 = blockIdx.x * 32;

    float acc[3][2][2] = {};

    for (int k0 = 0; k0 < 2 * UNITS; k0 += 32) {
        for (int i = tid; i < 32 * 32; i += 256) {
            int m = i >> 5, k = i & 31;
            As[m][k] = g_xc[(size_t)(row0 + m) * (2 * UNITS) + k0 + k];
        }
        for (int i = tid; i < 32 * 32; i += 256) {
            int k = i >> 5, n = i & 31;
            const float* src = gru_k + (size_t)(k0 + k) * (3 * UNITS) + col0 + n;
            Bs[0][k][n] = src[0];
            Bs[1][k][n] = src[UNITS];
            Bs[2][k][n] = src[2 * UNITS];
        }
        __syncthreads();
        #pragma unroll 8
        for (int kk = 0; kk < 32; kk++) {
            float a0 = As[tr * 2][kk], a1 = As[tr * 2 + 1][kk];
            #pragma unroll
            for (int g = 0; g < 3; g++) {
                float b0 = Bs[g][kk][tc * 2], b1 = Bs[g][kk][tc * 2 + 1];
                acc[g][0][0] += a0 * b0; acc[g][0][1] += a0 * b1;
                acc[g][1][0] += a1 * b0; acc[g][1][1] += a1 * b1;
            }
        }
        __syncthreads();
    }

    const float* b0v = gru_b;
    const float* b1v = gru_b + 3 * UNITS;
    #pragma unroll
    for (int ii = 0; ii < 2; ii++) {
        #pragma unroll
        for (int jj = 0; jj < 2; jj++) {
            int u = col0 + tc * 2 + jj;
            int rowi = row0 + tr * 2 + ii;
            float z  = sigmoidf_(acc[0][ii][jj] + b0v[u] + b1v[u]);
            float rr = sigmoidf_(acc[1][ii][jj] + b0v[UNITS + u] + b1v[UNITS + u]);
            float hh = tanhf(acc[2][ii][jj] + b0v[2 * UNITS + u] + rr * b1v[2 * UNITS + u]);
            out_state[(size_t)rowi * UNITS + u] = (1.0f - z) * hh;
        }
    }
}

// ---------------- fp32 SGEMM for y = relu(state@dW + db) ------------------
template<int BM, int BN, int BK, int TM, int TN, int ACT>
__global__ void sgemm_kernel(const float* __restrict__ A, const float* __restrict__ B,
                             const float* __restrict__ bias, float* __restrict__ C,
                             int M, int N, int K)
{
    constexpr int TCOLS = BN / TN;
    constexpr int TROWS = BM / TM;
    constexpr int NT = TROWS * TCOLS;
    __shared__ float As[BK][BM];
    __shared__ float Bs[BK][BN];

    int tid = threadIdx.x;
    int tr = tid / TCOLS;
    int tc = tid % TCOLS;
    int row0 = blockIdx.y * BM;
    int col0 = blockIdx.x * BN;

    float acc[TM][TN] = {};

    for (int k0 = 0; k0 < K; k0 += BK) {
        for (int idx = tid; idx < BM * BK; idx += NT) {
            int m = idx / BK, k = idx % BK;
            As[k][m] = A[(size_t)(row0 + m) * K + k0 + k];
        }
        for (int idx = tid; idx < BK * BN; idx += NT) {
            int k = idx / BN, n = idx % BN;
            Bs[k][n] = B[(size_t)(k0 + k) * N + col0 + n];
        }
        __syncthreads();
        #pragma unroll
        for (int kk = 0; kk < BK; kk++) {
            float ra[TM], rb[TN];
            #pragma unroll
            for (int i = 0; i < TM; i++) ra[i] = As[kk][tr + i * TROWS];
            #pragma unroll
            for (int j = 0; j < TN; j++) rb[j] = Bs[kk][tc + j * TCOLS];
            #pragma unroll
            for (int i = 0; i < TM; i++)
                #pragma unroll
                for (int j = 0; j < TN; j++) acc[i][j] += ra[i] * rb[j];
        }
        __syncthreads();
    }

    #pragma unroll
    for (int i = 0; i < TM; i++) {
        int rr = row0 + tr + i * TROWS;
        #pragma unroll
        for (int j = 0; j < TN; j++) {
            int cc = col0 + tc + j * TCOLS;
            float v = acc[i][j] + bias[cc];
            if (ACT == 1) v = fmaxf(v, 0.0f);
            C[(size_t)rr * N + cc] = v;
        }
    }
}

// ---------------- launch ----------------
extern "C" void kernel_launch(void* const* d_in, const int* in_sizes, int n_in,
                              void* d_out, int out_size) {
    const int*   inp    = (const int*)d_in[0];
    const float* attn   = (const float*)d_in[1];
    const float* W0     = (const float*)d_in[2];
    const float* b0     = (const float*)d_in[3];
    const float* b1     = (const float*)d_in[5];
    const float* vW     = (const float*)d_in[6];
    const float* emb    = (const float*)d_in[8];
    const float* gru_k  = (const float*)d_in[9];
    const float* gru_b  = (const float*)d_in[11];
    const float* dW     = (const float*)d_in[12];
    const float* db     = (const float*)d_in[13];
    const float* oW     = (const float*)d_in[14];
    const float* ob     = (const float*)d_in[15];

    float* out        = (float*)d_out;
    float* out_logits = out;
    float* out_state  = out + (size_t)BATCH * VOCAB;
    float* out_alpha  = out + (size_t)BATCH * VOCAB + (size_t)BATCH * UNITS;

    float *p_score, *p_y;
    cudaGetSymbolAddress((void**)&p_score, g_score);
    cudaGetSymbolAddress((void**)&p_y,     g_y);

    cudaFuncSetAttribute(tf32_gemm<1, 0>, cudaFuncAttributeMaxDynamicSharedMemorySize,
                         (int)GEMM_SMEM_BYTES);
    cudaFuncSetAttribute(tf32_gemm<0, 0>, cudaFuncAttributeMaxDynamicSharedMemorySize,
                         (int)GEMM_SMEM_BYTES);

    // 1. attention scores: tanh(attn@W0 + b0 + b1).vW  (vb dropped: softmax-invariant)
    cudaMemsetAsync(p_score, 0, ROWS * sizeof(float));
    tf32_gemm<1, 0><<<dim3(UNITS / 128, ROWS / 128), 256, GEMM_SMEM_BYTES>>>(
        attn, W0, b0, nullptr, ROWS, UNITS, UNITS, b1, vW);

    // 2. softmax + context + emb gather (writes g_xc, out_alpha)
    attn_reduce_kernel<<<BATCH, 256>>>(attn, inp, emb, out_alpha);

    // 3. gates GEMM + GRU nonlinearity -> state
    gru_fused_kernel<<<dim3(UNITS / 32, BATCH / 32), 256>>>(gru_k, gru_b, out_state);

    // 4. y = relu(state @ dW + db)
    sgemm_kernel<32, 32, 32, 2, 2, 1><<<dim3(UNITS / 32, BATCH / 32), 256>>>(
        out_state, dW, db, p_y, BATCH, UNITS, UNITS);

    // 5. logits = y @ oW + ob
    tf32_gemm<0, 0><<<dim3(VOCAB / 128, BATCH / 128), 256, GEMM_SMEM_BYTES>>>(
        p_y, oW, ob, out_logits, BATCH, VOCAB, UNITS, nullptr, nullptr);
}